// round 1
// baseline (speedup 1.0000x reference)
#include <cuda_runtime.h>
#include <cuda_bf16.h>
#include <cstdint>

// out[i, s] = sigmoid( sqrt(sum_j X[i,j]^2 * exp(lv[j])) * z[s] + sum_j X[i,j]*mu[j] )
// N = 500000, D = 64, NS = 128.
//
// One warp per row:
//   - lane l holds X[i, 2l], X[i, 2l+1]  (float2 load, 256B/warp coalesced)
//   - per-lane constants: mu pair, exp(lv) pair, z quad (float4)
//   - butterfly-reduce mean & var
//   - lane l writes out[i, 4l .. 4l+3] as one float4 (512B/warp coalesced)

__device__ __forceinline__ float fast_sigmoid(float a) {
    // 1 / (1 + exp(-a)); exp(-a)->inf for very negative a gives 0, ->0 gives 1. OK.
    float e = __expf(-a);
    return __fdividef(1.0f, 1.0f + e);
}

__device__ __forceinline__ float fast_sqrt(float v) {
    float s;
    asm("sqrt.approx.f32 %0, %1;" : "=f"(s) : "f"(v));
    return s;
}

__global__ __launch_bounds__(256) void blr_sigmoid_kernel(
    const float* __restrict__ X,
    const float* __restrict__ w_mu,
    const float* __restrict__ w_lv,
    const float* __restrict__ z,
    float* __restrict__ out,
    int n)
{
    const int lane = threadIdx.x & 31;
    const int warp_global = (blockIdx.x * blockDim.x + threadIdx.x) >> 5;

    // Per-lane constants (same for every row this warp touches).
    const float2 mu = reinterpret_cast<const float2*>(w_mu)[lane];
    const float2 lv = reinterpret_cast<const float2*>(w_lv)[lane];
    const float2 ew = make_float2(__expf(lv.x), __expf(lv.y));
    const float4 zv = reinterpret_cast<const float4*>(z)[lane];

    int row = warp_global;
    if (row >= n) return;

    const float2 x = reinterpret_cast<const float2*>(X + (size_t)row * 64)[lane];

    float m = fmaf(x.x, mu.x, x.y * mu.y);
    float v = fmaf(x.x * x.x, ew.x, (x.y * x.y) * ew.y);

    #pragma unroll
    for (int o = 16; o > 0; o >>= 1) {
        m += __shfl_xor_sync(0xffffffffu, m, o);
        v += __shfl_xor_sync(0xffffffffu, v, o);
    }

    const float s = fast_sqrt(v);

    float4 r;
    r.x = fast_sigmoid(fmaf(s, zv.x, m));
    r.y = fast_sigmoid(fmaf(s, zv.y, m));
    r.z = fast_sigmoid(fmaf(s, zv.z, m));
    r.w = fast_sigmoid(fmaf(s, zv.w, m));

    reinterpret_cast<float4*>(out + (size_t)row * 128)[lane] = r;
}

extern "C" void kernel_launch(void* const* d_in, const int* in_sizes, int n_in,
                              void* d_out, int out_size) {
    const float* X    = (const float*)d_in[0];
    const float* w_mu = (const float*)d_in[1];
    const float* w_lv = (const float*)d_in[2];
    const float* z    = (const float*)d_in[3];
    float* out = (float*)d_out;

    const int n = in_sizes[0] / 64;            // 500000 rows
    const int warps_per_block = 256 / 32;      // 8 rows per block
    const int blocks = (n + warps_per_block - 1) / warps_per_block;

    blr_sigmoid_kernel<<<blocks, 256>>>(X, w_mu, w_lv, z, out, n);
}

// round 2
// speedup vs baseline: 1.2132x; 1.2132x over previous
#include <cuda_runtime.h>
#include <cuda_bf16.h>
#include <cstdint>

// out[i, s] = sigmoid( sqrt(sum_j X[i,j]^2 * exp(lv[j])) * z[s] + sum_j X[i,j]*mu[j] )
// N = 500000 rows, D = 64, NS = 128.
//
// Layout: half-warp per row. Lanes 0-15 -> row r, lanes 16-31 -> row r+1.
//   - lane loads float4 of its row: one LDG.128 warp-instr = 2 full rows (512B)
//   - butterfly reduce over 16 lanes (offsets 8,4,2,1) serves both rows at once
//   - each warp processes 2 row-pairs (4 rows) with both loads hoisted (MLP=2)
//   - sigmoid via MUFU.TANH: sigmoid(a) = 0.5*tanh(a/2) + 0.5  (1 MUFU/elem)
//   - lane writes 2x float4 per row -> STG.128, 2x256B contiguous segments/warp-instr

__device__ __forceinline__ float fast_tanh(float a) {
    float t;
    asm("tanh.approx.f32 %0, %1;" : "=f"(t) : "f"(a));
    return t;
}

__device__ __forceinline__ float fast_sqrt(float v) {
    float s;
    asm("sqrt.approx.f32 %0, %1;" : "=f"(s) : "f"(v));
    return s;
}

__device__ __forceinline__ void dot_pair(const float4& x, const float4& mu,
                                         const float4& ew, float& m, float& v) {
    m = x.x * mu.x;
    m = fmaf(x.y, mu.y, m);
    m = fmaf(x.z, mu.z, m);
    m = fmaf(x.w, mu.w, m);
    v = (x.x * x.x) * ew.x;
    v = fmaf(x.y * x.y, ew.y, v);
    v = fmaf(x.z * x.z, ew.z, v);
    v = fmaf(x.w * x.w, ew.w, v);
}

__global__ __launch_bounds__(256) void blr_sigmoid_kernel(
    const float* __restrict__ X,
    const float* __restrict__ w_mu,
    const float* __restrict__ w_lv,
    const float* __restrict__ z,
    float* __restrict__ out,
    int n)
{
    const int lane = threadIdx.x & 31;
    const int hl   = lane & 15;          // position within half-warp
    const int half = lane >> 4;          // 0 or 1: which row of the pair
    const int warp_global = (blockIdx.x * blockDim.x + threadIdx.x) >> 5;

    // Per-lane constants
    const float4 mu4 = reinterpret_cast<const float4*>(w_mu)[hl];
    const float4 lv4 = reinterpret_cast<const float4*>(w_lv)[hl];
    const float4 ew4 = make_float4(__expf(lv4.x), __expf(lv4.y),
                                   __expf(lv4.z), __expf(lv4.w));
    const float4 zA = reinterpret_cast<const float4*>(z)[hl];
    const float4 zB = reinterpret_cast<const float4*>(z)[hl + 16];

    // This warp owns rows [base, base+3]; this lane's rows: base+half, base+2+half
    const int base = warp_global * 4;
    const int r0 = base + half;
    const int r1 = base + 2 + half;
    if (r1 >= n) {
        if (r0 >= n) return;
    }

    // Hoist both loads (MLP=2)
    float4 x0 = reinterpret_cast<const float4*>(X + (size_t)r0 * 64)[hl];
    float4 x1;
    const bool have1 = (r1 < n);
    if (have1) x1 = reinterpret_cast<const float4*>(X + (size_t)r1 * 64)[hl];

    float m0, v0, m1 = 0.f, v1 = 0.f;
    dot_pair(x0, mu4, ew4, m0, v0);
    if (have1) dot_pair(x1, mu4, ew4, m1, v1);

    // Butterfly over the 16-lane group; interleave all 4 chains for ILP
    #pragma unroll
    for (int o = 8; o > 0; o >>= 1) {
        m0 += __shfl_xor_sync(0xffffffffu, m0, o);
        v0 += __shfl_xor_sync(0xffffffffu, v0, o);
        m1 += __shfl_xor_sync(0xffffffffu, m1, o);
        v1 += __shfl_xor_sync(0xffffffffu, v1, o);
    }

    // sigmoid(a) = 0.5*tanh(a/2)+0.5 ; a/2 = (s/2)*z + (m/2)
    {
        const float sh = 0.5f * fast_sqrt(v0);
        const float mh = 0.5f * m0;
        float4 ra, rb;
        ra.x = fmaf(fast_tanh(fmaf(sh, zA.x, mh)), 0.5f, 0.5f);
        ra.y = fmaf(fast_tanh(fmaf(sh, zA.y, mh)), 0.5f, 0.5f);
        ra.z = fmaf(fast_tanh(fmaf(sh, zA.z, mh)), 0.5f, 0.5f);
        ra.w = fmaf(fast_tanh(fmaf(sh, zA.w, mh)), 0.5f, 0.5f);
        rb.x = fmaf(fast_tanh(fmaf(sh, zB.x, mh)), 0.5f, 0.5f);
        rb.y = fmaf(fast_tanh(fmaf(sh, zB.y, mh)), 0.5f, 0.5f);
        rb.z = fmaf(fast_tanh(fmaf(sh, zB.z, mh)), 0.5f, 0.5f);
        rb.w = fmaf(fast_tanh(fmaf(sh, zB.w, mh)), 0.5f, 0.5f);
        float4* o0 = reinterpret_cast<float4*>(out + (size_t)r0 * 128);
        o0[hl]      = ra;
        o0[hl + 16] = rb;
    }

    if (have1) {
        const float sh = 0.5f * fast_sqrt(v1);
        const float mh = 0.5f * m1;
        float4 ra, rb;
        ra.x = fmaf(fast_tanh(fmaf(sh, zA.x, mh)), 0.5f, 0.5f);
        ra.y = fmaf(fast_tanh(fmaf(sh, zA.y, mh)), 0.5f, 0.5f);
        ra.z = fmaf(fast_tanh(fmaf(sh, zA.z, mh)), 0.5f, 0.5f);
        ra.w = fmaf(fast_tanh(fmaf(sh, zA.w, mh)), 0.5f, 0.5f);
        rb.x = fmaf(fast_tanh(fmaf(sh, zB.x, mh)), 0.5f, 0.5f);
        rb.y = fmaf(fast_tanh(fmaf(sh, zB.y, mh)), 0.5f, 0.5f);
        rb.z = fmaf(fast_tanh(fmaf(sh, zB.z, mh)), 0.5f, 0.5f);
        rb.w = fmaf(fast_tanh(fmaf(sh, zB.w, mh)), 0.5f, 0.5f);
        float4* o1 = reinterpret_cast<float4*>(out + (size_t)r1 * 128);
        o1[hl]      = ra;
        o1[hl + 16] = rb;
    }
}

extern "C" void kernel_launch(void* const* d_in, const int* in_sizes, int n_in,
                              void* d_out, int out_size) {
    const float* X    = (const float*)d_in[0];
    const float* w_mu = (const float*)d_in[1];
    const float* w_lv = (const float*)d_in[2];
    const float* z    = (const float*)d_in[3];
    float* out = (float*)d_out;

    const int n = in_sizes[0] / 64;                  // 500000 rows
    const int rows_per_block = 4 * (256 / 32);       // 4 rows/warp * 8 warps
    const int blocks = (n + rows_per_block - 1) / rows_per_block;

    blr_sigmoid_kernel<<<blocks, 256>>>(X, w_mu, w_lv, z, out, n);
}